// round 1
// baseline (speedup 1.0000x reference)
#include <cuda_runtime.h>
#include <cstdint>

#define N_TOK 8192
#define DIM   2048
#define NEXP  8

#define BM 128
#define BN 128
#define BK 16
#define PAD 132   // smem row stride (floats) to break STS bank conflicts

// ---------------- scratch (static device globals; no allocations) ----------
__device__ int   g_count[NEXP];
__device__ int   g_tok[NEXP][N_TOK];
__device__ float g_wt[NEXP][N_TOK];
__device__ int   g_slot[NEXP][N_TOK];
__device__ float g_C[2ull * N_TOK * DIM];   // 134 MB: per-slot contributions

// ---------------- reset (graph replays must re-zero counts) ----------------
__global__ void reset_kernel() {
    if (threadIdx.x < NEXP) g_count[threadIdx.x] = 0;
}

// ---------------- gating: logits -> softmax -> top2 -> buckets -------------
// one warp per token
__global__ void gating_kernel(const float* __restrict__ x,
                              const float* __restrict__ Wg,
                              const float* __restrict__ bg) {
    int warp = (blockIdx.x * blockDim.x + threadIdx.x) >> 5;
    int lane = threadIdx.x & 31;
    if (warp >= N_TOK) return;

    const float4* xr = reinterpret_cast<const float4*>(x + (size_t)warp * DIM);
    float acc[NEXP];
#pragma unroll
    for (int e = 0; e < NEXP; e++) acc[e] = 0.f;

    for (int d4 = lane; d4 < DIM / 4; d4 += 32) {
        float4 xv = __ldg(&xr[d4]);
#pragma unroll
        for (int e = 0; e < NEXP; e++) {
            float4 wv = __ldg(&reinterpret_cast<const float4*>(Wg + (size_t)e * DIM)[d4]);
            acc[e] += xv.x * wv.x + xv.y * wv.y + xv.z * wv.z + xv.w * wv.w;
        }
    }
#pragma unroll
    for (int e = 0; e < NEXP; e++) {
#pragma unroll
        for (int off = 16; off > 0; off >>= 1)
            acc[e] += __shfl_xor_sync(0xffffffffu, acc[e], off);
    }

    if (lane == 0) {
        float lg[NEXP];
        float mx = -1e30f;
#pragma unroll
        for (int e = 0; e < NEXP; e++) { lg[e] = acc[e] + bg[e]; mx = fmaxf(mx, lg[e]); }
        float s = 0.f;
#pragma unroll
        for (int e = 0; e < NEXP; e++) { lg[e] = expf(lg[e] - mx); s += lg[e]; }
        float inv = 1.f / s;

        // top-2 by prob (== by logit), lowest-index tie-break like lax.top_k
        int e0 = 0;
#pragma unroll
        for (int e = 1; e < NEXP; e++) if (lg[e] > lg[e0]) e0 = e;
        int e1 = (e0 == 0) ? 1 : 0;
#pragma unroll
        for (int e = 0; e < NEXP; e++) if (e != e0 && lg[e] > lg[e1]) e1 = e;

        float w0 = lg[e0] * inv;
        float w1 = lg[e1] * inv;

        int p0 = atomicAdd(&g_count[e0], 1);
        g_tok[e0][p0] = warp; g_wt[e0][p0] = w0; g_slot[e0][p0] = 0;
        int p1 = atomicAdd(&g_count[e1], 1);
        g_tok[e1][p1] = warp; g_wt[e1][p1] = w1; g_slot[e1][p1] = 1;
    }
}

// ---------------- per-expert gathered GEMM + bias + relu + weight ----------
// C[slot][tok][:] = w * relu(x[tok] @ We[e]^T + be[e])
// grid: (DIM/BN, N_TOK/BM, NEXP); block: 256
__global__ __launch_bounds__(256, 2)
void expert_gemm_kernel(const float* __restrict__ x,
                        const float* __restrict__ We,
                        const float* __restrict__ be) {
    int e  = blockIdx.z;
    int Me = g_count[e];
    int m0 = blockIdx.y * BM;
    if (m0 >= Me) return;
    int n0 = blockIdx.x * BN;

    __shared__ float As[BK * PAD];
    __shared__ float Bs[BK * PAD];
    __shared__ int   tok_s[BM];
    __shared__ float w_s[BM];
    __shared__ int   slot_s[BM];

    int tid = threadIdx.x;
    if (tid < BM) {
        int gm = m0 + tid;
        if (gm < Me) {
            tok_s[tid]  = g_tok[e][gm];
            w_s[tid]    = g_wt[e][gm];
            slot_s[tid] = g_slot[e][gm];
        } else {
            tok_s[tid] = 0; w_s[tid] = 0.f; slot_s[tid] = 0;
        }
    }
    __syncthreads();

    const int lrow = tid >> 2;   // 0..63
    const int lcol = tid & 3;    // float4 column within BK
    const float* Wbase = We + (size_t)e * DIM * DIM;

    const int tokA0 = tok_s[lrow];
    const int tokA1 = tok_s[lrow + 64];

    const int ty = tid >> 4, tx = tid & 15;
    const int tm = ty * 8, tn = tx * 8;

    unsigned long long acc[8][4];
#pragma unroll
    for (int i = 0; i < 8; i++)
#pragma unroll
        for (int j = 0; j < 4; j++) acc[i][j] = 0ull;

    for (int k0 = 0; k0 < DIM; k0 += BK) {
        // global loads (overlap with previous tile's compute)
        float4 a0 = *(const float4*)(x + (size_t)tokA0 * DIM + k0 + lcol * 4);
        float4 a1 = *(const float4*)(x + (size_t)tokA1 * DIM + k0 + lcol * 4);
        float4 b0 = *(const float4*)(Wbase + (size_t)(n0 + lrow)      * DIM + k0 + lcol * 4);
        float4 b1 = *(const float4*)(Wbase + (size_t)(n0 + lrow + 64) * DIM + k0 + lcol * 4);

        __syncthreads();   // previous compute done before overwriting smem
        {
            int kk = lcol * 4;
            As[(kk + 0) * PAD + lrow] = a0.x;
            As[(kk + 1) * PAD + lrow] = a0.y;
            As[(kk + 2) * PAD + lrow] = a0.z;
            As[(kk + 3) * PAD + lrow] = a0.w;
            As[(kk + 0) * PAD + lrow + 64] = a1.x;
            As[(kk + 1) * PAD + lrow + 64] = a1.y;
            As[(kk + 2) * PAD + lrow + 64] = a1.z;
            As[(kk + 3) * PAD + lrow + 64] = a1.w;
            Bs[(kk + 0) * PAD + lrow] = b0.x;
            Bs[(kk + 1) * PAD + lrow] = b0.y;
            Bs[(kk + 2) * PAD + lrow] = b0.z;
            Bs[(kk + 3) * PAD + lrow] = b0.w;
            Bs[(kk + 0) * PAD + lrow + 64] = b1.x;
            Bs[(kk + 1) * PAD + lrow + 64] = b1.y;
            Bs[(kk + 2) * PAD + lrow + 64] = b1.z;
            Bs[(kk + 3) * PAD + lrow + 64] = b1.w;
        }
        __syncthreads();

#pragma unroll
        for (int k = 0; k < BK; k++) {
            float4 av0 = *(const float4*)&As[k * PAD + tm];
            float4 av1 = *(const float4*)&As[k * PAD + tm + 4];
            unsigned long long bp[4];
            bp[0] = *(const unsigned long long*)&Bs[k * PAD + tn + 0];
            bp[1] = *(const unsigned long long*)&Bs[k * PAD + tn + 2];
            bp[2] = *(const unsigned long long*)&Bs[k * PAD + tn + 4];
            bp[3] = *(const unsigned long long*)&Bs[k * PAD + tn + 6];
            float a[8] = {av0.x, av0.y, av0.z, av0.w, av1.x, av1.y, av1.z, av1.w};
#pragma unroll
            for (int i = 0; i < 8; i++) {
                unsigned long long ap;
                asm("mov.b64 %0, {%1, %1};" : "=l"(ap) : "f"(a[i]));
#pragma unroll
                for (int j = 0; j < 4; j++) {
                    asm("fma.rn.f32x2 %0, %1, %2, %0;"
                        : "+l"(acc[i][j]) : "l"(ap), "l"(bp[j]));
                }
            }
        }
    }

    // epilogue: bias + relu + gate-weight, scatter to per-slot scratch
    float bias[8];
#pragma unroll
    for (int j = 0; j < 8; j++)
        bias[j] = __ldg(&be[(size_t)e * DIM + n0 + tn + j]);

#pragma unroll
    for (int i = 0; i < 8; i++) {
        int r = tm + i;
        if (m0 + r >= Me) continue;
        float w   = w_s[r];
        float* dst = g_C + (size_t)slot_s[r] * N_TOK * DIM
                         + (size_t)tok_s[r] * DIM + n0 + tn;
        float v[8];
#pragma unroll
        for (int j = 0; j < 4; j++) {
            unsigned long long p = acc[i][j];
            v[2 * j + 0] = __uint_as_float((unsigned)(p & 0xffffffffull));
            v[2 * j + 1] = __uint_as_float((unsigned)(p >> 32));
        }
#pragma unroll
        for (int j = 0; j < 8; j++)
            v[j] = fmaxf(v[j] + bias[j], 0.f) * w;

        *(float4*)(dst + 0) = make_float4(v[0], v[1], v[2], v[3]);
        *(float4*)(dst + 4) = make_float4(v[4], v[5], v[6], v[7]);
    }
}

// ---------------- combine the two slots -----------------------------------
__global__ void combine_kernel(float* __restrict__ out) {
    size_t i = (size_t)blockIdx.x * blockDim.x + threadIdx.x;
    const float4* c0 = (const float4*)g_C;
    const float4* c1 = (const float4*)(g_C + (size_t)N_TOK * DIM);
    if (i < (size_t)N_TOK * DIM / 4) {
        float4 a = c0[i];
        float4 b = c1[i];
        ((float4*)out)[i] = make_float4(a.x + b.x, a.y + b.y, a.z + b.z, a.w + b.w);
    }
}

// ---------------- launch ----------------------------------------------------
extern "C" void kernel_launch(void* const* d_in, const int* in_sizes, int n_in,
                              void* d_out, int out_size) {
    const float* x  = (const float*)d_in[0];
    const float* We = (const float*)d_in[1];
    const float* be = (const float*)d_in[2];
    const float* Wg = (const float*)d_in[3];
    const float* bg = (const float*)d_in[4];
    float* out = (float*)d_out;

    reset_kernel<<<1, 32>>>();
    gating_kernel<<<N_TOK / 8, 256>>>(x, Wg, bg);
    expert_gemm_kernel<<<dim3(DIM / BN, N_TOK / BM, NEXP), 256>>>(x, We, be);
    combine_kernel<<<(N_TOK * DIM / 4) / 256, 256>>>(out);
}

// round 3
// speedup vs baseline: 2.5032x; 2.5032x over previous
#include <cuda_runtime.h>
#include <cuda_fp16.h>
#include <cstdint>

#define N_TOK 8192
#define DIM   2048
#define NEXP  8

#define BM 128
#define BN 128
#define BK 32                 // fp32/fp16 K elems per chunk
#define NCH (DIM / BK)        // 64

#define PITCH 80              // bytes per 32-fp16 row (64B data + 16B pad): conflict-free LDSM
#define TILE_A 10240          // 128 * 80
#define TILE_B 10240
#define ST_SIZE 30720         // Ahi + Alo + Bhi
#define OFF_TOK  61440
#define OFF_WT   61952
#define OFF_SLOT 62464
#define SMEM_BYTES 63488

// ---- scratch ---------------------------------------------------------------
__device__ int   g_count[NEXP];
__device__ int   g_tok[NEXP][N_TOK];
__device__ float g_wt[NEXP][N_TOK];
__device__ int   g_slot[NEXP][N_TOK];
__device__ float g_C[2ull * N_TOK * DIM];

// ---- helpers -----------------------------------------------------------------
__device__ __forceinline__ uint32_t smem_u32(const void* p) {
    return (uint32_t)__cvta_generic_to_shared(p);
}
__device__ __forceinline__ void ldsm4(uint32_t& r0, uint32_t& r1, uint32_t& r2,
                                      uint32_t& r3, uint32_t addr) {
    asm volatile("ldmatrix.sync.aligned.m8n8.x4.shared.b16 {%0,%1,%2,%3}, [%4];"
                 : "=r"(r0), "=r"(r1), "=r"(r2), "=r"(r3) : "r"(addr));
}
__device__ __forceinline__ void mma16816(float* c, const uint32_t* a, const uint32_t* b) {
    asm volatile(
        "mma.sync.aligned.m16n8k16.row.col.f32.f16.f16.f32 "
        "{%0,%1,%2,%3}, {%4,%5,%6,%7}, {%8,%9}, {%0,%1,%2,%3};"
        : "+f"(c[0]), "+f"(c[1]), "+f"(c[2]), "+f"(c[3])
        : "r"(a[0]), "r"(a[1]), "r"(a[2]), "r"(a[3]), "r"(b[0]), "r"(b[1]));
}
__device__ __forceinline__ uint32_t cvt_pair_hi(float a, float b, uint32_t& lo) {
    __half ha = __float2half_rn(a), hb = __float2half_rn(b);
    float  ra = a - __half2float(ha), rb = b - __half2float(hb);
    __half la = __float2half_rn(ra), lb = __float2half_rn(rb);
    lo = (uint32_t)(*(unsigned short*)&la) | ((uint32_t)(*(unsigned short*)&lb) << 16);
    return (uint32_t)(*(unsigned short*)&ha) | ((uint32_t)(*(unsigned short*)&hb) << 16);
}
__device__ __forceinline__ uint32_t cvt_pair(float a, float b) {
    __half ha = __float2half_rn(a), hb = __float2half_rn(b);
    return (uint32_t)(*(unsigned short*)&ha) | ((uint32_t)(*(unsigned short*)&hb) << 16);
}

// ---- reset -----------------------------------------------------------------
__global__ void reset_kernel() {
    if (threadIdx.x < NEXP) g_count[threadIdx.x] = 0;
}

// ---- gating (known good from R1) --------------------------------------------
__global__ void gating_kernel(const float* __restrict__ x,
                              const float* __restrict__ Wg,
                              const float* __restrict__ bg) {
    int warp = (blockIdx.x * blockDim.x + threadIdx.x) >> 5;
    int lane = threadIdx.x & 31;
    if (warp >= N_TOK) return;

    const float4* xr = reinterpret_cast<const float4*>(x + (size_t)warp * DIM);
    float acc[NEXP];
#pragma unroll
    for (int e = 0; e < NEXP; e++) acc[e] = 0.f;

    for (int d4 = lane; d4 < DIM / 4; d4 += 32) {
        float4 xv = __ldg(&xr[d4]);
#pragma unroll
        for (int e = 0; e < NEXP; e++) {
            float4 wv = __ldg(&reinterpret_cast<const float4*>(Wg + (size_t)e * DIM)[d4]);
            acc[e] += xv.x * wv.x + xv.y * wv.y + xv.z * wv.z + xv.w * wv.w;
        }
    }
#pragma unroll
    for (int e = 0; e < NEXP; e++) {
#pragma unroll
        for (int off = 16; off > 0; off >>= 1)
            acc[e] += __shfl_xor_sync(0xffffffffu, acc[e], off);
    }

    if (lane == 0) {
        float lg[NEXP];
        float mx = -1e30f;
#pragma unroll
        for (int e = 0; e < NEXP; e++) { lg[e] = acc[e] + bg[e]; mx = fmaxf(mx, lg[e]); }
        float s = 0.f;
#pragma unroll
        for (int e = 0; e < NEXP; e++) { lg[e] = expf(lg[e] - mx); s += lg[e]; }
        float inv = 1.f / s;

        int e0 = 0;
#pragma unroll
        for (int e = 1; e < NEXP; e++) if (lg[e] > lg[e0]) e0 = e;
        int e1 = (e0 == 0) ? 1 : 0;
#pragma unroll
        for (int e = 0; e < NEXP; e++) if (e != e0 && lg[e] > lg[e1]) e1 = e;

        int p0 = atomicAdd(&g_count[e0], 1);
        g_tok[e0][p0] = warp; g_wt[e0][p0] = lg[e0] * inv; g_slot[e0][p0] = 0;
        int p1 = atomicAdd(&g_count[e1], 1);
        g_tok[e1][p1] = warp; g_wt[e1][p1] = lg[e1] * inv; g_slot[e1][p1] = 1;
    }
}

// ---- fp16 2-term mma.sync expert GEMM ----------------------------------------
// acc = x_hi @ Whi^T + x_lo @ Whi^T  (x split exact to ~22 bits; W fp16)
__global__ __launch_bounds__(256, 1)
void expert_gemm_mma(const float* __restrict__ x,
                     const float* __restrict__ We,
                     const float* __restrict__ be) {
    extern __shared__ __align__(128) char smem[];

    const int e  = blockIdx.z;
    const int Me = g_count[e];
    const int m0 = blockIdx.y * BM;
    if (m0 >= Me) return;
    const int n0 = blockIdx.x * BN;

    const int tid  = threadIdx.x;
    const int wid  = tid >> 5;
    const int lane = tid & 31;

    int*   tok_s  = (int*)(smem + OFF_TOK);
    float* w_s    = (float*)(smem + OFF_WT);
    int*   slot_s = (int*)(smem + OFF_SLOT);

    if (tid < BM) {
        int gm = m0 + tid;
        if (gm < Me) {
            tok_s[tid] = g_tok[e][gm]; w_s[tid] = g_wt[e][gm]; slot_s[tid] = g_slot[e][gm];
        } else {
            tok_s[tid] = 0; w_s[tid] = 0.f; slot_s[tid] = 0;
        }
    }
    __syncthreads();

    // loader geometry: thread -> (row = r*32 + tid>>3, 4-fp32 granule = tid&7)
    const int lrow = tid >> 3;
    const int kc   = (tid & 7) * 4;
    const float* Wbase = We + (size_t)e * DIM * DIM;

    const float* aptr[4];
    const float* bptr[4];
#pragma unroll
    for (int r = 0; r < 4; r++) {
        aptr[r] = x + (size_t)tok_s[lrow + r * 32] * DIM + kc;
        bptr[r] = Wbase + (size_t)(n0 + lrow + r * 32) * DIM + kc;
    }
    const uint32_t sts_off = (uint32_t)(lrow * PITCH + (tid & 7) * 8);

    // warp tile
    const int wm = (wid & 3) * 32;
    const int wn = (wid >> 2) * 64;

    float acc[2][8][4];
#pragma unroll
    for (int mf = 0; mf < 2; mf++)
#pragma unroll
        for (int nf = 0; nf < 8; nf++)
#pragma unroll
            for (int j = 0; j < 4; j++) acc[mf][nf][j] = 0.f;

    // ldmatrix address components (per thread, constant)
    const uint32_t aRowAddr = (uint32_t)((wm + (lane & 15)) * PITCH + (lane >> 4) * 16);
    const uint32_t bRowAddr = (uint32_t)((wn + (lane & 7) + ((lane >> 4) << 3)) * PITCH +
                                         ((lane >> 3) & 1) * 16);
    const uint32_t sA  = smem_u32(smem);
    const uint32_t sAl = sA + TILE_A;
    const uint32_t sB  = sA + 2 * TILE_A;

    float4 aR[4], bR[4];
#pragma unroll
    for (int r = 0; r < 4; r++) {
        aR[r] = __ldg((const float4*)(aptr[r]));
        bR[r] = __ldg((const float4*)(bptr[r]));
    }
    // store chunk 0 into stage 0
    {
        char* base = smem;
#pragma unroll
        for (int r = 0; r < 4; r++) {
            uint32_t lo0, lo1;
            uint32_t h0 = cvt_pair_hi(aR[r].x, aR[r].y, lo0);
            uint32_t h1 = cvt_pair_hi(aR[r].z, aR[r].w, lo1);
            *(uint2*)(base + sts_off + r * 32 * PITCH)          = make_uint2(h0, h1);
            *(uint2*)(base + TILE_A + sts_off + r * 32 * PITCH) = make_uint2(lo0, lo1);
            uint32_t b0 = cvt_pair(bR[r].x, bR[r].y);
            uint32_t b1 = cvt_pair(bR[r].z, bR[r].w);
            *(uint2*)(base + 2 * TILE_A + sts_off + r * 32 * PITCH) = make_uint2(b0, b1);
        }
    }
    __syncthreads();

    for (int c = 0; c < NCH; c++) {
        const int st = c & 1;

        if (c + 1 < NCH) {
            const int k1 = (c + 1) * BK;
#pragma unroll
            for (int r = 0; r < 4; r++) {
                aR[r] = __ldg((const float4*)(aptr[r] + k1));
                bR[r] = __ldg((const float4*)(bptr[r] + k1));
            }
        }

        // compute chunk c from stage st
        const uint32_t bA  = sA  + st * ST_SIZE;
        const uint32_t bAl = sAl + st * ST_SIZE;
        const uint32_t bB  = sB  + st * ST_SIZE;
#pragma unroll
        for (int ks = 0; ks < 2; ks++) {
            const uint32_t kb = ks * 32;
            uint32_t ah[2][4], al[2][4], bb[8][2];
#pragma unroll
            for (int mf = 0; mf < 2; mf++) {
                ldsm4(ah[mf][0], ah[mf][1], ah[mf][2], ah[mf][3],
                      bA + aRowAddr + mf * 16 * PITCH + kb);
                ldsm4(al[mf][0], al[mf][1], al[mf][2], al[mf][3],
                      bAl + aRowAddr + mf * 16 * PITCH + kb);
            }
#pragma unroll
            for (int q = 0; q < 4; q++) {
                ldsm4(bb[2 * q][0], bb[2 * q][1], bb[2 * q + 1][0], bb[2 * q + 1][1],
                      bB + bRowAddr + q * 16 * PITCH + kb);
            }
#pragma unroll
            for (int mf = 0; mf < 2; mf++)
#pragma unroll
                for (int nf = 0; nf < 8; nf++) {
                    mma16816(acc[mf][nf], ah[mf], bb[nf]);
                    mma16816(acc[mf][nf], al[mf], bb[nf]);
                }
        }

        // store chunk c+1 into stage st^1
        if (c + 1 < NCH) {
            char* base = smem + (st ^ 1) * ST_SIZE;
#pragma unroll
            for (int r = 0; r < 4; r++) {
                uint32_t lo0, lo1;
                uint32_t h0 = cvt_pair_hi(aR[r].x, aR[r].y, lo0);
                uint32_t h1 = cvt_pair_hi(aR[r].z, aR[r].w, lo1);
                *(uint2*)(base + sts_off + r * 32 * PITCH)          = make_uint2(h0, h1);
                *(uint2*)(base + TILE_A + sts_off + r * 32 * PITCH) = make_uint2(lo0, lo1);
                uint32_t b0 = cvt_pair(bR[r].x, bR[r].y);
                uint32_t b1 = cvt_pair(bR[r].z, bR[r].w);
                *(uint2*)(base + 2 * TILE_A + sts_off + r * 32 * PITCH) = make_uint2(b0, b1);
            }
        }
        __syncthreads();
    }

    // ---- fused epilogue: bias + relu + gate weight, straight from C frags ----
#pragma unroll
    for (int mf = 0; mf < 2; mf++) {
        const int lm0 = wm + mf * 16 + (lane >> 2);
        const int lm1 = lm0 + 8;
        const bool ok0 = (m0 + lm0) < Me;
        const bool ok1 = (m0 + lm1) < Me;
        const float w0 = w_s[lm0], w1 = w_s[lm1];
        float* d0 = g_C + (size_t)slot_s[lm0] * N_TOK * DIM + (size_t)tok_s[lm0] * DIM;
        float* d1 = g_C + (size_t)slot_s[lm1] * N_TOK * DIM + (size_t)tok_s[lm1] * DIM;
#pragma unroll
        for (int nf = 0; nf < 8; nf++) {
            const int col = n0 + wn + nf * 8 + (lane & 3) * 2;
            const float b0 = __ldg(&be[(size_t)e * DIM + col]);
            const float b1 = __ldg(&be[(size_t)e * DIM + col + 1]);
            if (ok0) {
                float v0 = fmaxf(acc[mf][nf][0] + b0, 0.f) * w0;
                float v1 = fmaxf(acc[mf][nf][1] + b1, 0.f) * w0;
                *(float2*)(d0 + col) = make_float2(v0, v1);
            }
            if (ok1) {
                float v2 = fmaxf(acc[mf][nf][2] + b0, 0.f) * w1;
                float v3 = fmaxf(acc[mf][nf][3] + b1, 0.f) * w1;
                *(float2*)(d1 + col) = make_float2(v2, v3);
            }
        }
    }
}

// ---- combine -----------------------------------------------------------------
__global__ void combine_kernel(float* __restrict__ out) {
    size_t i = (size_t)blockIdx.x * blockDim.x + threadIdx.x;
    const float4* c0 = (const float4*)g_C;
    const float4* c1 = (const float4*)(g_C + (size_t)N_TOK * DIM);
    if (i < (size_t)N_TOK * DIM / 4) {
        float4 a = c0[i];
        float4 b = c1[i];
        ((float4*)out)[i] = make_float4(a.x + b.x, a.y + b.y, a.z + b.z, a.w + b.w);
    }
}

// ---- launch --------------------------------------------------------------------
extern "C" void kernel_launch(void* const* d_in, const int* in_sizes, int n_in,
                              void* d_out, int out_size) {
    const float* x  = (const float*)d_in[0];
    const float* We = (const float*)d_in[1];
    const float* be = (const float*)d_in[2];
    const float* Wg = (const float*)d_in[3];
    const float* bg = (const float*)d_in[4];
    float* out = (float*)d_out;

    cudaFuncSetAttribute(expert_gemm_mma,
                         cudaFuncAttributeMaxDynamicSharedMemorySize, SMEM_BYTES);

    reset_kernel<<<1, 32>>>();
    gating_kernel<<<N_TOK / 8, 256>>>(x, Wg, bg);
    expert_gemm_mma<<<dim3(DIM / BN, N_TOK / BM, NEXP), 256, SMEM_BYTES>>>(x, We, be);
    combine_kernel<<<(N_TOK * DIM / 4) / 256, 256>>>(out);
}

// round 4
// speedup vs baseline: 5.3738x; 2.1468x over previous
#include <cuda_runtime.h>
#include <cuda_fp16.h>
#include <cstdint>

#define N_TOK 8192
#define DIM   2048
#define NEXP  8

#define BM 128
#define BN 256
#define BK 64                  // fp16 K elems per chunk (128B row)
#define NCH (DIM / BK)         // 32
#define NSTAGE 3

#define PITCH 144              // 128B data + 16B pad -> conflict-free LDSM
#define A_TILE (BM * PITCH)    // 18432
#define B_TILE (BN * PITCH)    // 36864
#define ST_SIZE (A_TILE + B_TILE)   // 55296
#define OFF_TOK  (NSTAGE * ST_SIZE)       // 165888
#define OFF_WT   (OFF_TOK + 512)
#define OFF_SLOT (OFF_WT + 512)
#define SMEM_BYTES (OFF_SLOT + 512)

// ---- scratch ---------------------------------------------------------------
__device__ int   g_count[NEXP];
__device__ int   g_tok[NEXP][N_TOK];
__device__ float g_wt[NEXP][N_TOK];
__device__ int   g_slot[NEXP][N_TOK];
__device__ float g_C[2ull * N_TOK * DIM];
__device__ __align__(16) __half g_Wh[(size_t)NEXP * DIM * DIM];
__device__ __align__(16) __half g_Xh[(size_t)N_TOK * DIM];

// ---- helpers -----------------------------------------------------------------
__device__ __forceinline__ uint32_t smem_u32(const void* p) {
    return (uint32_t)__cvta_generic_to_shared(p);
}
__device__ __forceinline__ void cp16(uint32_t dst, const void* src) {
    asm volatile("cp.async.ca.shared.global [%0], [%1], 16;" :: "r"(dst), "l"(src));
}
__device__ __forceinline__ void cp_commit() {
    asm volatile("cp.async.commit_group;" ::: "memory");
}
template <int N>
__device__ __forceinline__ void cp_wait() {
    asm volatile("cp.async.wait_group %0;" :: "n"(N) : "memory");
}
__device__ __forceinline__ void ldsm4(uint32_t& r0, uint32_t& r1, uint32_t& r2,
                                      uint32_t& r3, uint32_t addr) {
    asm volatile("ldmatrix.sync.aligned.m8n8.x4.shared.b16 {%0,%1,%2,%3}, [%4];"
                 : "=r"(r0), "=r"(r1), "=r"(r2), "=r"(r3) : "r"(addr));
}
__device__ __forceinline__ void mma16816(float* c, const uint32_t* a, const uint32_t* b) {
    asm volatile(
        "mma.sync.aligned.m16n8k16.row.col.f32.f16.f16.f32 "
        "{%0,%1,%2,%3}, {%4,%5,%6,%7}, {%8,%9}, {%0,%1,%2,%3};"
        : "+f"(c[0]), "+f"(c[1]), "+f"(c[2]), "+f"(c[3])
        : "r"(a[0]), "r"(a[1]), "r"(a[2]), "r"(a[3]), "r"(b[0]), "r"(b[1]));
}

// ---- reset -----------------------------------------------------------------
__global__ void reset_kernel() {
    if (threadIdx.x < NEXP) g_count[threadIdx.x] = 0;
}

// ---- fp32 -> fp16 converters (one-time, out of hot loop) ---------------------
__global__ void convert_f32_f16(const float* __restrict__ src,
                                __half* __restrict__ dst, size_t n4) {
    size_t i = (size_t)blockIdx.x * blockDim.x + threadIdx.x;
    if (i < n4) {
        float4 v = __ldg(((const float4*)src) + i);
        __half2 a = __floats2half2_rn(v.x, v.y);
        __half2 b = __floats2half2_rn(v.z, v.w);
        ((uint2*)dst)[i] = make_uint2(*(uint32_t*)&a, *(uint32_t*)&b);
    }
}

// ---- gating (known good) ------------------------------------------------------
__global__ void gating_kernel(const float* __restrict__ x,
                              const float* __restrict__ Wg,
                              const float* __restrict__ bg) {
    int warp = (blockIdx.x * blockDim.x + threadIdx.x) >> 5;
    int lane = threadIdx.x & 31;
    if (warp >= N_TOK) return;

    const float4* xr = reinterpret_cast<const float4*>(x + (size_t)warp * DIM);
    float acc[NEXP];
#pragma unroll
    for (int e = 0; e < NEXP; e++) acc[e] = 0.f;

    for (int d4 = lane; d4 < DIM / 4; d4 += 32) {
        float4 xv = __ldg(&xr[d4]);
#pragma unroll
        for (int e = 0; e < NEXP; e++) {
            float4 wv = __ldg(&reinterpret_cast<const float4*>(Wg + (size_t)e * DIM)[d4]);
            acc[e] += xv.x * wv.x + xv.y * wv.y + xv.z * wv.z + xv.w * wv.w;
        }
    }
#pragma unroll
    for (int e = 0; e < NEXP; e++) {
#pragma unroll
        for (int off = 16; off > 0; off >>= 1)
            acc[e] += __shfl_xor_sync(0xffffffffu, acc[e], off);
    }

    if (lane == 0) {
        float lg[NEXP];
        float mx = -1e30f;
#pragma unroll
        for (int e = 0; e < NEXP; e++) { lg[e] = acc[e] + bg[e]; mx = fmaxf(mx, lg[e]); }
        float s = 0.f;
#pragma unroll
        for (int e = 0; e < NEXP; e++) { lg[e] = expf(lg[e] - mx); s += lg[e]; }
        float inv = 1.f / s;

        int e0 = 0;
#pragma unroll
        for (int e = 1; e < NEXP; e++) if (lg[e] > lg[e0]) e0 = e;
        int e1 = (e0 == 0) ? 1 : 0;
#pragma unroll
        for (int e = 0; e < NEXP; e++) if (e != e0 && lg[e] > lg[e1]) e1 = e;

        int p0 = atomicAdd(&g_count[e0], 1);
        g_tok[e0][p0] = warp; g_wt[e0][p0] = lg[e0] * inv; g_slot[e0][p0] = 0;
        int p1 = atomicAdd(&g_count[e1], 1);
        g_tok[e1][p1] = warp; g_wt[e1][p1] = lg[e1] * inv; g_slot[e1][p1] = 1;
    }
}

// ---- fp16 mma.sync expert GEMM, cp.async 3-stage pipeline ---------------------
// 512 threads, tile 128x256xK64, warp tile 32x64 (4x4 warps)
__global__ __launch_bounds__(512, 1)
void expert_gemm_mma(const float* __restrict__ be) {
    extern __shared__ __align__(128) char smem[];

    const int e  = blockIdx.z;
    const int Me = g_count[e];
    const int m0 = blockIdx.y * BM;
    if (m0 >= Me) return;
    const int n0 = blockIdx.x * BN;

    const int tid  = threadIdx.x;
    const int wid  = tid >> 5;
    const int lane = tid & 31;

    int*   tok_s  = (int*)(smem + OFF_TOK);
    float* w_s    = (float*)(smem + OFF_WT);
    int*   slot_s = (int*)(smem + OFF_SLOT);

    if (tid < BM) {
        int gm = m0 + tid;
        if (gm < Me) {
            tok_s[tid] = g_tok[e][gm]; w_s[tid] = g_wt[e][gm]; slot_s[tid] = g_slot[e][gm];
        } else {
            tok_s[tid] = 0; w_s[tid] = 0.f; slot_s[tid] = 0;
        }
    }
    __syncthreads();

    // loader geometry: 512 threads; row = tid>>2, chunk pair = (tid&3), (tid&3)+4
    const int lr  = tid >> 2;        // 0..127
    const int lc  = tid & 3;         // 16B chunk index (and +4)
    const __half* Asrc = g_Xh + (size_t)tok_s[lr] * DIM + lc * 8;
    const __half* Bbase = g_Wh + (size_t)e * DIM * DIM;
    const __half* Bsrc0 = Bbase + (size_t)(n0 + lr) * DIM + lc * 8;
    const __half* Bsrc1 = Bbase + (size_t)(n0 + 128 + lr) * DIM + lc * 8;

    const uint32_t sbase = smem_u32(smem);
    const uint32_t a_dst = sbase + lr * PITCH + lc * 16;
    const uint32_t b_dst0 = sbase + A_TILE + lr * PITCH + lc * 16;
    const uint32_t b_dst1 = sbase + A_TILE + (128 + lr) * PITCH + lc * 16;

    // warp tile
    const int wm = (wid & 3) * 32;
    const int wn = (wid >> 2) * 64;

    float acc[2][8][4];
#pragma unroll
    for (int mf = 0; mf < 2; mf++)
#pragma unroll
        for (int nf = 0; nf < 8; nf++)
#pragma unroll
            for (int j = 0; j < 4; j++) acc[mf][nf][j] = 0.f;

    const uint32_t aRowAddr = (uint32_t)((wm + (lane & 15)) * PITCH + (lane >> 4) * 16);
    const uint32_t bRowAddr = (uint32_t)((wn + (lane & 7) + ((lane >> 4) << 3)) * PITCH +
                                         ((lane >> 3) & 1) * 16);

    // prologue: issue NSTAGE stages
#pragma unroll
    for (int c = 0; c < NSTAGE; c++) {
        const uint32_t so = c * ST_SIZE;
        const int k0 = c * BK;
        cp16(a_dst + so,       Asrc + k0);
        cp16(a_dst + so + 64,  Asrc + k0 + 32);
        cp16(b_dst0 + so,      Bsrc0 + k0);
        cp16(b_dst0 + so + 64, Bsrc0 + k0 + 32);
        cp16(b_dst1 + so,      Bsrc1 + k0);
        cp16(b_dst1 + so + 64, Bsrc1 + k0 + 32);
        cp_commit();
    }

    int st = 0;
    for (int c = 0; c < NCH; c++) {
        cp_wait<NSTAGE - 1>();
        __syncthreads();

        const uint32_t bA = sbase + st * ST_SIZE;
        const uint32_t bB = bA + A_TILE;
#pragma unroll
        for (int ks = 0; ks < 4; ks++) {
            const uint32_t kb = ks * 32;
            uint32_t ah[2][4], bb[8][2];
#pragma unroll
            for (int mf = 0; mf < 2; mf++)
                ldsm4(ah[mf][0], ah[mf][1], ah[mf][2], ah[mf][3],
                      bA + aRowAddr + mf * 16 * PITCH + kb);
#pragma unroll
            for (int q = 0; q < 4; q++)
                ldsm4(bb[2 * q][0], bb[2 * q][1], bb[2 * q + 1][0], bb[2 * q + 1][1],
                      bB + bRowAddr + q * 16 * PITCH + kb);
#pragma unroll
            for (int mf = 0; mf < 2; mf++)
#pragma unroll
                for (int nf = 0; nf < 8; nf++)
                    mma16816(acc[mf][nf], ah[mf], bb[nf]);
        }
        __syncthreads();

        if (c + NSTAGE < NCH) {
            const uint32_t so = st * ST_SIZE;
            const int k0 = (c + NSTAGE) * BK;
            cp16(a_dst + so,       Asrc + k0);
            cp16(a_dst + so + 64,  Asrc + k0 + 32);
            cp16(b_dst0 + so,      Bsrc0 + k0);
            cp16(b_dst0 + so + 64, Bsrc0 + k0 + 32);
            cp16(b_dst1 + so,      Bsrc1 + k0);
            cp16(b_dst1 + so + 64, Bsrc1 + k0 + 32);
        }
        cp_commit();   // commit every iteration to keep group accounting aligned

        st = (st + 1 == NSTAGE) ? 0 : st + 1;
    }

    // ---- fused epilogue: bias + relu + gate weight ------------------------------
#pragma unroll
    for (int mf = 0; mf < 2; mf++) {
        const int lm0 = wm + mf * 16 + (lane >> 2);
        const int lm1 = lm0 + 8;
        const bool ok0 = (m0 + lm0) < Me;
        const bool ok1 = (m0 + lm1) < Me;
        const float w0 = w_s[lm0], w1 = w_s[lm1];
        float* d0 = g_C + (size_t)slot_s[lm0] * N_TOK * DIM + (size_t)tok_s[lm0] * DIM;
        float* d1 = g_C + (size_t)slot_s[lm1] * N_TOK * DIM + (size_t)tok_s[lm1] * DIM;
#pragma unroll
        for (int nf = 0; nf < 8; nf++) {
            const int col = n0 + wn + nf * 8 + (lane & 3) * 2;
            const float b0 = __ldg(&be[(size_t)e * DIM + col]);
            const float b1 = __ldg(&be[(size_t)e * DIM + col + 1]);
            if (ok0) {
                float v0 = fmaxf(acc[mf][nf][0] + b0, 0.f) * w0;
                float v1 = fmaxf(acc[mf][nf][1] + b1, 0.f) * w0;
                *(float2*)(d0 + col) = make_float2(v0, v1);
            }
            if (ok1) {
                float v2 = fmaxf(acc[mf][nf][2] + b0, 0.f) * w1;
                float v3 = fmaxf(acc[mf][nf][3] + b1, 0.f) * w1;
                *(float2*)(d1 + col) = make_float2(v2, v3);
            }
        }
    }
}

// ---- combine -------------------------------------------------------------------
__global__ void combine_kernel(float* __restrict__ out) {
    size_t i = (size_t)blockIdx.x * blockDim.x + threadIdx.x;
    const float4* c0 = (const float4*)g_C;
    const float4* c1 = (const float4*)(g_C + (size_t)N_TOK * DIM);
    if (i < (size_t)N_TOK * DIM / 4) {
        float4 a = c0[i];
        float4 b = c1[i];
        ((float4*)out)[i] = make_float4(a.x + b.x, a.y + b.y, a.z + b.z, a.w + b.w);
    }
}

// ---- launch ----------------------------------------------------------------------
extern "C" void kernel_launch(void* const* d_in, const int* in_sizes, int n_in,
                              void* d_out, int out_size) {
    const float* x  = (const float*)d_in[0];
    const float* We = (const float*)d_in[1];
    const float* be = (const float*)d_in[2];
    const float* Wg = (const float*)d_in[3];
    const float* bg = (const float*)d_in[4];
    float* out = (float*)d_out;

    cudaFuncSetAttribute(expert_gemm_mma,
                         cudaFuncAttributeMaxDynamicSharedMemorySize, SMEM_BYTES);

    __half* wh; cudaGetSymbolAddress((void**)&wh, g_Wh);
    __half* xh; cudaGetSymbolAddress((void**)&xh, g_Xh);

    reset_kernel<<<1, 32>>>();
    convert_f32_f16<<<((size_t)NEXP * DIM * DIM / 4 + 255) / 256, 256>>>(We, wh, (size_t)NEXP * DIM * DIM / 4);
    convert_f32_f16<<<((size_t)N_TOK * DIM / 4 + 255) / 256, 256>>>(x, xh, (size_t)N_TOK * DIM / 4);
    gating_kernel<<<N_TOK / 8, 256>>>(x, Wg, bg);
    expert_gemm_mma<<<dim3(DIM / BN, N_TOK / BM, NEXP), 512, SMEM_BYTES>>>(be);
    combine_kernel<<<(N_TOK * DIM / 4) / 256, 256>>>(out);
}